// round 9
// baseline (speedup 1.0000x reference)
#include <cuda_runtime.h>
#include <math.h>
#include <stdint.h>

// ---------------------------------------------------------------------------
// FedTGPClientLoss:
//   ce    = mean_b [ logsumexp(logits[b,:]) - logits[b, label_b] ]   (0 if !finite)
//   proto = mean_b mean_d (features[b,d] - protos[label_b, d])^2
//   total = ce + proto                                               (ce if !finite)
// Output: [total, ce, proto]  (3 x f32)
//
// One WARP per row. ALL loads (logits 8xfloat4, features 4xfloat4,
// protos 4xfloat4 per lane) batch-issued up front for maximum MLP; then
// single-pass sum-of-exp (no max subtraction; warp-uniform two-pass fallback
// for |logit|>~88) and MSE FMAs. Fused grid reduction via threadfence.
// ---------------------------------------------------------------------------

#define MAXBLK 8192
__device__ double   g_pce[MAXBLK];
__device__ double   g_pms[MAXBLK];
__device__ unsigned g_count = 0;   // reset by the last block each call

#define NEG_INF (-__int_as_float(0x7f800000))

__global__ __launch_bounds__(256, 3) void row_kernel(
    const float* __restrict__ logits,
    const int*   __restrict__ l32,     // labels viewed as int32 words
    const float* __restrict__ features,
    const float* __restrict__ protos,
    float* __restrict__ out,
    int B, int C, int D)
{
    const int lane = threadIdx.x & 31;
    const int wid  = threadIdx.x >> 5;
    const int row  = blockIdx.x * 8 + wid;
    const bool active = (row < B);

    float ce_f = 0.0f, ms_f = 0.0f;

    if (active) {
        // ---- per-warp label dtype detection (first 64 int32 words = 256B) ----
        // int64 labels < C  =>  all odd (high) words are 0.
        // int32 labels uniform [0,C)  =>  P(32 odd words all zero) ~ C^-32 ~ 0.
        int probe = l32[2 * lane + 1];
        bool lbl64 = (__ballot_sync(0xFFFFFFFFu, probe != 0) == 0u);
        const int label = lbl64 ? l32[2 * row] : l32[row];

        const float* lr = logits + (size_t)row * C;
        const float4* lrow = (const float4*)lr;
        const int C4 = C >> 2;
        const int Ctail = C & 3;
        const int D4 = D >> 2;

        float s = 0.0f, sq = 0.0f;

        if (C4 <= 256 && D4 == 128) {
            // ================= fast path: everything register-resident =====
            // 1) batch-issue 8 logits float4 loads
            float4 v[8];
            #pragma unroll
            for (int j = 0; j < 8; j++) {
                int idx = j * 32 + lane;
                v[j] = (idx < C4) ? lrow[idx]
                                  : make_float4(NEG_INF, NEG_INF, NEG_INF, NEG_INF);
            }
            float tval = (lane < Ctail) ? lr[C4 * 4 + lane] : NEG_INF;

            // 2) batch-issue feature + proto loads (4 float4 each per lane)
            const float4* frow = (const float4*)(features + (size_t)row   * D);
            const float4* prow = (const float4*)(protos   + (size_t)label * D);
            float4 f[4], p[4];
            #pragma unroll
            for (int j = 0; j < 4; j++) {
                f[j] = frow[j * 32 + lane];
                p[j] = prow[j * 32 + lane];
            }
            const float lbl_logit = __ldg(lr + label);   // warp-uniform

            // 3) exps: 4 independent accumulator chains
            float s0 = 0.f, s1 = 0.f, s2 = 0.f, s3 = 0.f;
            #pragma unroll
            for (int j = 0; j < 8; j++) {
                s0 += __expf(v[j].x);
                s1 += __expf(v[j].y);
                s2 += __expf(v[j].z);
                s3 += __expf(v[j].w);
            }
            s = (s0 + s1) + (s2 + s3) + __expf(tval);   // exp(-inf)=0 pads

            // 4) MSE FMAs
            #pragma unroll
            for (int j = 0; j < 4; j++) {
                float dx = f[j].x - p[j].x, dy = f[j].y - p[j].y;
                float dz = f[j].z - p[j].z, dw = f[j].w - p[j].w;
                sq = fmaf(dx, dx, fmaf(dy, dy, fmaf(dz, dz, fmaf(dw, dw, sq))));
            }

            // ---- warp sum reductions ----
            #pragma unroll
            for (int off = 16; off > 0; off >>= 1) {
                s  += __shfl_xor_sync(0xFFFFFFFFu, s,  off);
                sq += __shfl_xor_sync(0xFFFFFFFFu, sq, off);
            }

            float lse;
            if (__builtin_expect(isinf(s) || !(s > 0.0f), 0)) {
                // rare fallback: two-pass max-subtracted logsumexp (cache-hot)
                float m = NEG_INF;
                for (int idx = lane; idx < C4; idx += 32) {
                    float4 q = lrow[idx];
                    m = fmaxf(m, fmaxf(fmaxf(q.x, q.y), fmaxf(q.z, q.w)));
                }
                if (lane < Ctail) m = fmaxf(m, lr[C4 * 4 + lane]);
                #pragma unroll
                for (int off = 16; off > 0; off >>= 1)
                    m = fmaxf(m, __shfl_xor_sync(0xFFFFFFFFu, m, off));
                float t = 0.0f;
                for (int idx = lane; idx < C4; idx += 32) {
                    float4 q = lrow[idx];
                    t += __expf(q.x - m) + __expf(q.y - m)
                       + __expf(q.z - m) + __expf(q.w - m);
                }
                if (lane < Ctail) t += __expf(lr[C4 * 4 + lane] - m);
                #pragma unroll
                for (int off = 16; off > 0; off >>= 1)
                    t += __shfl_xor_sync(0xFFFFFFFFu, t, off);
                lse = m + __logf(t);
            } else {
                lse = __logf(s);
            }
            ce_f = lse - lbl_logit;
            ms_f = sq / (float)D;
        } else {
            // ================= generic path =================
            const float lbl_logit = __ldg(lr + label);
            for (int idx = lane; idx < C4; idx += 32) {
                float4 q = lrow[idx];
                s += __expf(q.x) + __expf(q.y) + __expf(q.z) + __expf(q.w);
            }
            if (lane < Ctail) s += __expf(lr[C4 * 4 + lane]);

            const float4* frow = (const float4*)(features + (size_t)row   * D);
            const float4* prow = (const float4*)(protos   + (size_t)label * D);
            for (int idx = lane; idx < D4; idx += 32) {
                float4 ff = frow[idx];
                float4 pp = prow[idx];
                float dx = ff.x - pp.x, dy = ff.y - pp.y;
                float dz = ff.z - pp.z, dw = ff.w - pp.w;
                sq = fmaf(dx, dx, fmaf(dy, dy, fmaf(dz, dz, fmaf(dw, dw, sq))));
            }
            const int Dtail = D & 3;
            if (lane < Dtail) {
                float d = features[(size_t)row * D + D4 * 4 + lane]
                        - protos[(size_t)label * D + D4 * 4 + lane];
                sq = fmaf(d, d, sq);
            }

            #pragma unroll
            for (int off = 16; off > 0; off >>= 1) {
                s  += __shfl_xor_sync(0xFFFFFFFFu, s,  off);
                sq += __shfl_xor_sync(0xFFFFFFFFu, sq, off);
            }

            float lse;
            if (__builtin_expect(isinf(s) || !(s > 0.0f), 0)) {
                float m = NEG_INF;
                for (int idx = lane; idx < C4; idx += 32) {
                    float4 q = lrow[idx];
                    m = fmaxf(m, fmaxf(fmaxf(q.x, q.y), fmaxf(q.z, q.w)));
                }
                if (lane < Ctail) m = fmaxf(m, lr[C4 * 4 + lane]);
                #pragma unroll
                for (int off = 16; off > 0; off >>= 1)
                    m = fmaxf(m, __shfl_xor_sync(0xFFFFFFFFu, m, off));
                float t = 0.0f;
                for (int idx = lane; idx < C4; idx += 32) {
                    float4 q = lrow[idx];
                    t += __expf(q.x - m) + __expf(q.y - m)
                       + __expf(q.z - m) + __expf(q.w - m);
                }
                if (lane < Ctail) t += __expf(lr[C4 * 4 + lane] - m);
                #pragma unroll
                for (int off = 16; off > 0; off >>= 1)
                    t += __shfl_xor_sync(0xFFFFFFFFu, t, off);
                lse = m + __logf(t);
            } else {
                lse = __logf(s);
            }
            ce_f = lse - lbl_logit;
            ms_f = sq / (float)D;
        }
    }

    // ---- block reduction of the 8 warp results (doubles) ----
    __shared__ double sm_ce[8], sm_ms[8];
    __shared__ bool   s_is_last;
    if (lane == 0) { sm_ce[wid] = (double)ce_f; sm_ms[wid] = (double)ms_f; }
    __syncthreads();

    if (threadIdx.x == 0) {
        double bce = 0.0, bms = 0.0;
        #pragma unroll
        for (int j = 0; j < 8; j++) { bce += sm_ce[j]; bms += sm_ms[j]; }
        g_pce[blockIdx.x] = bce;
        g_pms[blockIdx.x] = bms;
        __threadfence();
        unsigned prev = atomicAdd(&g_count, 1u);
        s_is_last = (prev == gridDim.x - 1);
    }
    __syncthreads();

    // ---- last-arriving block: reduce L2-hot partials, emit outputs ----
    if (s_is_last) {
        const int tid = threadIdx.x;
        const int nb  = gridDim.x;
        double ce = 0.0, ms = 0.0;
        for (int i = tid; i < nb; i += 256) { ce += g_pce[i]; ms += g_pms[i]; }

        __shared__ double red[512];
        red[tid] = ce; red[256 + tid] = ms;
        __syncthreads();
        #pragma unroll
        for (int off = 128; off > 0; off >>= 1) {
            if (tid < off) {
                red[tid]       += red[tid + off];
                red[256 + tid] += red[256 + tid + off];
            }
            __syncthreads();
        }

        if (tid == 0) {
            float ce_loss = (float)(red[0] / (double)B);
            if (!isfinite(ce_loss)) ce_loss = 0.0f;
            float proto_loss = (float)(red[256] / (double)B);
            float total = ce_loss + proto_loss;
            if (!isfinite(total)) total = ce_loss;
            out[0] = total;
            out[1] = ce_loss;
            out[2] = proto_loss;
            g_count = 0;          // reset for next graph replay
        }
    }
}

extern "C" void kernel_launch(void* const* d_in, const int* in_sizes, int n_in,
                              void* d_out, int out_size) {
    const float* logits   = (const float*)d_in[0];
    const int*   labels   = (const int*)d_in[1];
    const float* features = (const float*)d_in[2];
    const float* protos   = (const float*)d_in[3];
    float* out = (float*)d_out;

    const int B = in_sizes[1];                 // 16384
    const int C = in_sizes[0] / B;             // 1000
    const int D = in_sizes[2] / B;             // 512

    const int blocks = (B + 7) / 8;            // one warp per row, 8 warps/block
    row_kernel<<<blocks, 256>>>(logits, labels, features, protos, out, B, C, D);
}

// round 10
// speedup vs baseline: 1.0077x; 1.0077x over previous
#include <cuda_runtime.h>
#include <math.h>
#include <stdint.h>

// ---------------------------------------------------------------------------
// FedTGPClientLoss:
//   ce    = mean_b [ logsumexp(logits[b,:]) - logits[b, label_b] ]   (0 if !finite)
//   proto = mean_b mean_d (features[b,d] - protos[label_b, d])^2
//   total = ce + proto                                               (ce if !finite)
// Output: [total, ce, proto]  (3 x f32)
//
// One warp per 8 consecutive rows, software-pipelined: next row's logits are
// loaded into the alternate register buffer while the current row computes;
// feature/proto loads are issued at row start and consumed after the exps.
// Loads stay continuously in flight (fixes the ~50% DRAM duty cycle of the
// one-row-per-warp versions). Single-pass sum-of-exp (no max subtraction;
// warp-uniform two-pass fallback for |logit|>~88). Fused grid reduction.
// ---------------------------------------------------------------------------

#define MAXBLK 8192
__device__ double   g_pce[MAXBLK];
__device__ double   g_pms[MAXBLK];
__device__ unsigned g_count = 0;   // reset by the last block each call

#define NEG_INF (-__int_as_float(0x7f800000))
#define ROWS_PER_WARP 8

__global__ __launch_bounds__(128, 3) void row_kernel(
    const float* __restrict__ logits,
    const int*   __restrict__ l32,     // labels viewed as int32 words
    const float* __restrict__ features,
    const float* __restrict__ protos,
    float* __restrict__ out,
    int B, int C, int D)
{
    const int lane = threadIdx.x & 31;
    const int wid  = threadIdx.x >> 5;            // 0..3
    const int gw   = blockIdx.x * 4 + wid;        // global warp id
    const int base = gw * ROWS_PER_WARP;

    // ---- per-warp label dtype detection (first 64 int32 words) ----
    // int64 labels < C  =>  all odd (high) words are 0.
    // int32 labels uniform [0,C)  =>  P(32 odd words all zero) ~ C^-32 ~ 0.
    {
    }
    int pidx = 2 * lane + 1;
    int probe = (pidx < B) ? l32[pidx] : 0;
    const bool lbl64 = (__ballot_sync(0xFFFFFFFFu, probe != 0) == 0u);

    const int C4 = C >> 2, Ctail = C & 3, D4 = D >> 2;
    double ce_sum = 0.0, ms_sum = 0.0;            // lane0 accumulators

    const bool fast = (C4 <= 256) && (D4 == 128) && (base < B);

    if (fast) {
        float4 v0[8], v1[8];

        // ---- one pipelined row step (compute from vc, prefetch into vn) ----
        auto step = [&](int i, float4* vc, float4* vn, int& label_cur) {
            const int row = base + i;
            const bool rv = (row < B);
            const int r  = rv ? row : (B - 1);
            const float* lr = logits + (size_t)r * C;

            // issue current row's feature/proto loads (consumed after exps)
            const float4* frow = (const float4*)(features + (size_t)r * D);
            const float4* prow = (const float4*)(protos + (size_t)label_cur * D);
            float4 f[4], p[4];
            #pragma unroll
            for (int j = 0; j < 4; j++) {
                f[j] = frow[j * 32 + lane];
                p[j] = prow[j * 32 + lane];
            }
            const float lbl_logit = __ldg(lr + label_cur);
            const float tval = (lane < Ctail) ? lr[C4 * 4 + lane] : NEG_INF;

            // prefetch next row's logits + label into the alternate buffer
            int label_next = label_cur;
            if (i + 1 < ROWS_PER_WARP) {
                int nr = row + 1; if (nr >= B) nr = B - 1;
                label_next = lbl64 ? l32[2 * nr] : l32[nr];
                const float4* ln = (const float4*)(logits + (size_t)nr * C);
                #pragma unroll
                for (int j = 0; j < 8; j++) {
                    int idx = j * 32 + lane;
                    vn[j] = (idx < C4) ? ln[idx]
                                       : make_float4(NEG_INF, NEG_INF, NEG_INF, NEG_INF);
                }
            }

            // exps: 4 independent accumulator chains
            float s0 = 0.f, s1 = 0.f, s2 = 0.f, s3 = 0.f;
            #pragma unroll
            for (int j = 0; j < 8; j++) {
                s0 += __expf(vc[j].x);
                s1 += __expf(vc[j].y);
                s2 += __expf(vc[j].z);
                s3 += __expf(vc[j].w);
            }
            float s = (s0 + s1) + (s2 + s3) + __expf(tval);  // exp(-inf)=0 pads

            // MSE FMAs
            float sq = 0.f;
            #pragma unroll
            for (int j = 0; j < 4; j++) {
                float dx = f[j].x - p[j].x, dy = f[j].y - p[j].y;
                float dz = f[j].z - p[j].z, dw = f[j].w - p[j].w;
                sq = fmaf(dx, dx, fmaf(dy, dy, fmaf(dz, dz, fmaf(dw, dw, sq))));
            }

            // warp reductions
            #pragma unroll
            for (int off = 16; off > 0; off >>= 1) {
                s  += __shfl_xor_sync(0xFFFFFFFFu, s,  off);
                sq += __shfl_xor_sync(0xFFFFFFFFu, sq, off);
            }

            float lse;
            if (__builtin_expect(isinf(s) || !(s > 0.0f), 0)) {
                // rare fallback: two-pass max-subtracted logsumexp (cache-hot)
                const float4* lrow = (const float4*)lr;
                float m = NEG_INF;
                for (int idx = lane; idx < C4; idx += 32) {
                    float4 q = lrow[idx];
                    m = fmaxf(m, fmaxf(fmaxf(q.x, q.y), fmaxf(q.z, q.w)));
                }
                if (lane < Ctail) m = fmaxf(m, lr[C4 * 4 + lane]);
                #pragma unroll
                for (int off = 16; off > 0; off >>= 1)
                    m = fmaxf(m, __shfl_xor_sync(0xFFFFFFFFu, m, off));
                float t = 0.0f;
                for (int idx = lane; idx < C4; idx += 32) {
                    float4 q = lrow[idx];
                    t += __expf(q.x - m) + __expf(q.y - m)
                       + __expf(q.z - m) + __expf(q.w - m);
                }
                if (lane < Ctail) t += __expf(lr[C4 * 4 + lane] - m);
                #pragma unroll
                for (int off = 16; off > 0; off >>= 1)
                    t += __shfl_xor_sync(0xFFFFFFFFu, t, off);
                lse = m + __logf(t);
            } else {
                lse = __logf(s);
            }

            if (lane == 0 && rv) {
                ce_sum += (double)(lse - lbl_logit);
                ms_sum += (double)(sq / (float)D);
            }
            label_cur = label_next;
        };

        // prologue: load logits of row `base` into v0
        int label_cur = lbl64 ? l32[2 * base] : l32[base];
        {
            const float4* lq = (const float4*)(logits + (size_t)base * C);
            #pragma unroll
            for (int j = 0; j < 8; j++) {
                int idx = j * 32 + lane;
                v0[j] = (idx < C4) ? lq[idx]
                                   : make_float4(NEG_INF, NEG_INF, NEG_INF, NEG_INF);
            }
        }

        // pair loop keeps buffers in static registers with compact code
        for (int ii = 0; ii < ROWS_PER_WARP / 2; ii++) {
            step(2 * ii,     v0, v1, label_cur);
            step(2 * ii + 1, v1, v0, label_cur);
        }
    } else if (base < B) {
        // ================= generic path: one row at a time =================
        for (int i = 0; i < ROWS_PER_WARP; i++) {
            const int row = base + i;
            if (row >= B) break;
            const int label = lbl64 ? l32[2 * row] : l32[row];
            const float* lr = logits + (size_t)row * C;
            const float4* lrow = (const float4*)lr;
            const float lbl_logit = __ldg(lr + label);

            float s = 0.0f;
            for (int idx = lane; idx < C4; idx += 32) {
                float4 q = lrow[idx];
                s += __expf(q.x) + __expf(q.y) + __expf(q.z) + __expf(q.w);
            }
            if (lane < Ctail) s += __expf(lr[C4 * 4 + lane]);

            const float4* frow = (const float4*)(features + (size_t)row   * D);
            const float4* prow = (const float4*)(protos   + (size_t)label * D);
            float sq = 0.0f;
            for (int idx = lane; idx < D4; idx += 32) {
                float4 ff = frow[idx];
                float4 pp = prow[idx];
                float dx = ff.x - pp.x, dy = ff.y - pp.y;
                float dz = ff.z - pp.z, dw = ff.w - pp.w;
                sq = fmaf(dx, dx, fmaf(dy, dy, fmaf(dz, dz, fmaf(dw, dw, sq))));
            }
            const int Dtail = D & 3;
            if (lane < Dtail) {
                float d = features[(size_t)row * D + D4 * 4 + lane]
                        - protos[(size_t)label * D + D4 * 4 + lane];
                sq = fmaf(d, d, sq);
            }

            #pragma unroll
            for (int off = 16; off > 0; off >>= 1) {
                s  += __shfl_xor_sync(0xFFFFFFFFu, s,  off);
                sq += __shfl_xor_sync(0xFFFFFFFFu, sq, off);
            }

            float lse;
            if (__builtin_expect(isinf(s) || !(s > 0.0f), 0)) {
                float m = NEG_INF;
                for (int idx = lane; idx < C4; idx += 32) {
                    float4 q = lrow[idx];
                    m = fmaxf(m, fmaxf(fmaxf(q.x, q.y), fmaxf(q.z, q.w)));
                }
                if (lane < Ctail) m = fmaxf(m, lr[C4 * 4 + lane]);
                #pragma unroll
                for (int off = 16; off > 0; off >>= 1)
                    m = fmaxf(m, __shfl_xor_sync(0xFFFFFFFFu, m, off));
                float t = 0.0f;
                for (int idx = lane; idx < C4; idx += 32) {
                    float4 q = lrow[idx];
                    t += __expf(q.x - m) + __expf(q.y - m)
                       + __expf(q.z - m) + __expf(q.w - m);
                }
                if (lane < Ctail) t += __expf(lr[C4 * 4 + lane] - m);
                #pragma unroll
                for (int off = 16; off > 0; off >>= 1)
                    t += __shfl_xor_sync(0xFFFFFFFFu, t, off);
                lse = m + __logf(t);
            } else {
                lse = __logf(s);
            }
            if (lane == 0) {
                ce_sum += (double)(lse - lbl_logit);
                ms_sum += (double)(sq / (float)D);
            }
        }
    }

    // ---- block reduction of the 4 warp sums ----
    __shared__ double sm_ce[4], sm_ms[4];
    __shared__ bool   s_is_last;
    if (lane == 0) { sm_ce[wid] = ce_sum; sm_ms[wid] = ms_sum; }
    __syncthreads();

    if (threadIdx.x == 0) {
        double bce = 0.0, bms = 0.0;
        #pragma unroll
        for (int j = 0; j < 4; j++) { bce += sm_ce[j]; bms += sm_ms[j]; }
        g_pce[blockIdx.x] = bce;
        g_pms[blockIdx.x] = bms;
        __threadfence();
        unsigned prev = atomicAdd(&g_count, 1u);
        s_is_last = (prev == gridDim.x - 1);
    }
    __syncthreads();

    // ---- last-arriving block: reduce L2-hot partials, emit outputs ----
    if (s_is_last) {
        const int tid = threadIdx.x;
        const int nb  = gridDim.x;
        double ce = 0.0, ms = 0.0;
        for (int i = tid; i < nb; i += 128) { ce += g_pce[i]; ms += g_pms[i]; }

        __shared__ double red[256];
        red[tid] = ce; red[128 + tid] = ms;
        __syncthreads();
        #pragma unroll
        for (int off = 64; off > 0; off >>= 1) {
            if (tid < off) {
                red[tid]       += red[tid + off];
                red[128 + tid] += red[128 + tid + off];
            }
            __syncthreads();
        }

        if (tid == 0) {
            float ce_loss = (float)(red[0] / (double)B);
            if (!isfinite(ce_loss)) ce_loss = 0.0f;
            float proto_loss = (float)(red[128] / (double)B);
            float total = ce_loss + proto_loss;
            if (!isfinite(total)) total = ce_loss;
            out[0] = total;
            out[1] = ce_loss;
            out[2] = proto_loss;
            g_count = 0;          // reset for next graph replay
        }
    }
}

extern "C" void kernel_launch(void* const* d_in, const int* in_sizes, int n_in,
                              void* d_out, int out_size) {
    const float* logits   = (const float*)d_in[0];
    const int*   labels   = (const int*)d_in[1];
    const float* features = (const float*)d_in[2];
    const float* protos   = (const float*)d_in[3];
    float* out = (float*)d_out;

    const int B = in_sizes[1];                 // 16384
    const int C = in_sizes[0] / B;             // 1000
    const int D = in_sizes[2] / B;             // 512

    const int rows_per_block = 4 * ROWS_PER_WARP;   // 4 warps x 8 rows
    const int blocks = (B + rows_per_block - 1) / rows_per_block;
    row_kernel<<<blocks, 128>>>(logits, labels, features, protos, out, B, C, D);
}

// round 11
// speedup vs baseline: 1.0088x; 1.0011x over previous
#include <cuda_runtime.h>
#include <math.h>
#include <stdint.h>

// ---------------------------------------------------------------------------
// FedTGPClientLoss:
//   ce    = mean_b [ logsumexp(logits[b,:]) - logits[b, label_b] ]   (0 if !finite)
//   proto = mean_b mean_d (features[b,d] - protos[label_b, d])^2
//   total = ce + proto                                               (ce if !finite)
// Output: [total, ce, proto]  (3 x f32)
//
// One warp per 4 consecutive rows. Logits stream via cp.async double-buffered
// smem tiles (zero register cost for in-flight data): row i+1's LDGSTS group
// is committed before row i's compute begins, so the global-load stream never
// pauses. Features/protos are register LDGs issued at row start, consumed
// after the exps. Single-pass sum-of-exp (warp-uniform two-pass fallback for
// |logit|>~88). Fused grid reduction via threadfence pattern.
// ---------------------------------------------------------------------------

#define MAXBLK 8192
__device__ double   g_pce[MAXBLK];
__device__ double   g_pms[MAXBLK];
__device__ unsigned g_count = 0;   // reset by the last block each call

#define NEG_INF (-__int_as_float(0x7f800000))
#define ROWS_PER_WARP 4
#define WARPS_PER_BLK 4

__device__ __forceinline__ uint32_t smem_u32(const void* p) {
    return (uint32_t)__cvta_generic_to_shared(p);
}
__device__ __forceinline__ void cp16(uint32_t s, const void* g, int pred) {
    asm volatile(
        "{ .reg .pred p; setp.ne.u32 p, %2, 0;"
        " @p cp.async.cg.shared.global [%0], [%1], 16; }"
        :: "r"(s), "l"(g), "r"(pred));
}
#define CP_COMMIT() asm volatile("cp.async.commit_group;" ::: "memory")
#define CP_WAIT(n)  asm volatile("cp.async.wait_group %0;" :: "n"(n) : "memory")

__global__ __launch_bounds__(128, 7) void row_kernel(
    const float* __restrict__ logits,
    const int*   __restrict__ l32,     // labels viewed as int32 words
    const float* __restrict__ features,
    const float* __restrict__ protos,
    float* __restrict__ out,
    int B, int C, int D)
{
    __shared__ float4 tile[WARPS_PER_BLK][2][256];   // 32 KB

    const int lane = threadIdx.x & 31;
    const int wid  = threadIdx.x >> 5;               // 0..3
    const int base = (blockIdx.x * WARPS_PER_BLK + wid) * ROWS_PER_WARP;

    // ---- per-warp label dtype detection (first 64 int32 words) ----
    // int64 labels < C  =>  all odd (high) words are 0.
    // int32 labels uniform [0,C)  =>  P(32 odd words all zero) ~ C^-32 ~ 0.
    int pidx = 2 * lane + 1;
    int probe = (pidx < B) ? l32[pidx] : 0;
    const bool lbl64 = (__ballot_sync(0xFFFFFFFFu, probe != 0) == 0u);

    const int C4 = C >> 2, Ctail = C & 3, D4 = D >> 2;
    double ce_sum = 0.0, ms_sum = 0.0;               // lane0 accumulators

    const bool fast = (C4 <= 256) && (Ctail == 0) && (D4 == 128) && (base < B);

    if (fast) {
        // labels for this warp's rows, one per lane 0..3
        int lab_reg = 0;
        if (lane < ROWS_PER_WARP) {
            int r = base + lane; if (r >= B) r = B - 1;
            lab_reg = lbl64 ? l32[2 * r] : l32[r];
        }

        // prologue: cp.async row `base` into buffer 0
        {
            const float4* src = (const float4*)(logits + (size_t)base * C);
            #pragma unroll
            for (int j = 0; j < 8; j++) {
                int idx = j * 32 + lane;
                cp16(smem_u32(&tile[wid][0][idx]), src + idx, idx < C4);
            }
            CP_COMMIT();
        }

        #pragma unroll
        for (int i = 0; i < ROWS_PER_WARP; i++) {
            const int row = base + i;
            const bool rv = (row < B);
            const int buf = i & 1;
            const int label = __shfl_sync(0xFFFFFFFFu, lab_reg, i);

            // commit next row's logits into the alternate buffer
            const bool has_next = (i + 1 < ROWS_PER_WARP);
            if (has_next) {
                int nr = row + 1; if (nr >= B) nr = B - 1;
                const float4* src = (const float4*)(logits + (size_t)nr * C);
                #pragma unroll
                for (int j = 0; j < 8; j++) {
                    int idx = j * 32 + lane;
                    cp16(smem_u32(&tile[wid][buf ^ 1][idx]), src + idx, idx < C4);
                }
                CP_COMMIT();
            }

            // issue this row's feature/proto register loads now
            const int r = rv ? row : (B - 1);
            const float4* frow = (const float4*)(features + (size_t)r * D);
            const float4* prow = (const float4*)(protos + (size_t)label * D);
            float4 f[4], p[4];
            #pragma unroll
            for (int j = 0; j < 4; j++) {
                f[j] = frow[j * 32 + lane];
                p[j] = prow[j * 32 + lane];
            }

            // wait for THIS row's logits group (leave next in flight)
            if (has_next) { CP_WAIT(1); } else { CP_WAIT(0); }
            __syncwarp();

            const float* tb = (const float*)&tile[wid][buf][0];
            const float lbl_logit = tb[label];        // broadcast LDS

            // exps: 4 independent accumulator chains
            float s0 = 0.f, s1 = 0.f, s2 = 0.f, s3 = 0.f;
            #pragma unroll
            for (int j = 0; j < 8; j++) {
                int idx = j * 32 + lane;
                if (idx < C4) {
                    float4 v = tile[wid][buf][idx];
                    s0 += __expf(v.x);
                    s1 += __expf(v.y);
                    s2 += __expf(v.z);
                    s3 += __expf(v.w);
                }
            }
            float s = (s0 + s1) + (s2 + s3);

            // MSE FMAs
            float sq = 0.f;
            #pragma unroll
            for (int j = 0; j < 4; j++) {
                float dx = f[j].x - p[j].x, dy = f[j].y - p[j].y;
                float dz = f[j].z - p[j].z, dw = f[j].w - p[j].w;
                sq = fmaf(dx, dx, fmaf(dy, dy, fmaf(dz, dz, fmaf(dw, dw, sq))));
            }

            // warp reductions
            #pragma unroll
            for (int off = 16; off > 0; off >>= 1) {
                s  += __shfl_xor_sync(0xFFFFFFFFu, s,  off);
                sq += __shfl_xor_sync(0xFFFFFFFFu, sq, off);
            }

            float lse;
            if (__builtin_expect(isinf(s) || !(s > 0.0f), 0)) {
                // rare fallback: two-pass max-subtracted logsumexp (smem-hot)
                float m = NEG_INF;
                #pragma unroll
                for (int j = 0; j < 8; j++) {
                    int idx = j * 32 + lane;
                    if (idx < C4) {
                        float4 q = tile[wid][buf][idx];
                        m = fmaxf(m, fmaxf(fmaxf(q.x, q.y), fmaxf(q.z, q.w)));
                    }
                }
                #pragma unroll
                for (int off = 16; off > 0; off >>= 1)
                    m = fmaxf(m, __shfl_xor_sync(0xFFFFFFFFu, m, off));
                float t = 0.0f;
                #pragma unroll
                for (int j = 0; j < 8; j++) {
                    int idx = j * 32 + lane;
                    if (idx < C4) {
                        float4 q = tile[wid][buf][idx];
                        t += __expf(q.x - m) + __expf(q.y - m)
                           + __expf(q.z - m) + __expf(q.w - m);
                    }
                }
                #pragma unroll
                for (int off = 16; off > 0; off >>= 1)
                    t += __shfl_xor_sync(0xFFFFFFFFu, t, off);
                lse = m + __logf(t);
            } else {
                lse = __logf(s);
            }

            if (lane == 0 && rv) {
                ce_sum += (double)(lse - lbl_logit);
                ms_sum += (double)(sq / (float)D);
            }
        }
    } else if (base < B) {
        // ================= generic path: one row at a time =================
        for (int i = 0; i < ROWS_PER_WARP; i++) {
            const int row = base + i;
            if (row >= B) break;
            const int label = lbl64 ? l32[2 * row] : l32[row];
            const float* lr = logits + (size_t)row * C;
            const float4* lrow = (const float4*)lr;
            const float lbl_logit = __ldg(lr + label);

            float s = 0.0f;
            for (int idx = lane; idx < C4; idx += 32) {
                float4 q = lrow[idx];
                s += __expf(q.x) + __expf(q.y) + __expf(q.z) + __expf(q.w);
            }
            if (lane < Ctail) s += __expf(lr[C4 * 4 + lane]);

            const float4* frow = (const float4*)(features + (size_t)row   * D);
            const float4* prow = (const float4*)(protos   + (size_t)label * D);
            float sq = 0.0f;
            for (int idx = lane; idx < D4; idx += 32) {
                float4 ff = frow[idx];
                float4 pp = prow[idx];
                float dx = ff.x - pp.x, dy = ff.y - pp.y;
                float dz = ff.z - pp.z, dw = ff.w - pp.w;
                sq = fmaf(dx, dx, fmaf(dy, dy, fmaf(dz, dz, fmaf(dw, dw, sq))));
            }
            const int Dtail = D & 3;
            if (lane < Dtail) {
                float d = features[(size_t)row * D + D4 * 4 + lane]
                        - protos[(size_t)label * D + D4 * 4 + lane];
                sq = fmaf(d, d, sq);
            }

            #pragma unroll
            for (int off = 16; off > 0; off >>= 1) {
                s  += __shfl_xor_sync(0xFFFFFFFFu, s,  off);
                sq += __shfl_xor_sync(0xFFFFFFFFu, sq, off);
            }

            float lse;
            if (__builtin_expect(isinf(s) || !(s > 0.0f), 0)) {
                float m = NEG_INF;
                for (int idx = lane; idx < C4; idx += 32) {
                    float4 q = lrow[idx];
                    m = fmaxf(m, fmaxf(fmaxf(q.x, q.y), fmaxf(q.z, q.w)));
                }
                if (lane < Ctail) m = fmaxf(m, lr[C4 * 4 + lane]);
                #pragma unroll
                for (int off = 16; off > 0; off >>= 1)
                    m = fmaxf(m, __shfl_xor_sync(0xFFFFFFFFu, m, off));
                float t = 0.0f;
                for (int idx = lane; idx < C4; idx += 32) {
                    float4 q = lrow[idx];
                    t += __expf(q.x - m) + __expf(q.y - m)
                       + __expf(q.z - m) + __expf(q.w - m);
                }
                if (lane < Ctail) t += __expf(lr[C4 * 4 + lane] - m);
                #pragma unroll
                for (int off = 16; off > 0; off >>= 1)
                    t += __shfl_xor_sync(0xFFFFFFFFu, t, off);
                lse = m + __logf(t);
            } else {
                lse = __logf(s);
            }
            if (lane == 0) {
                ce_sum += (double)(lse - lbl_logit);
                ms_sum += (double)(sq / (float)D);
            }
        }
    }

    // ---- block reduction of the 4 warp sums ----
    __shared__ double sm_ce[WARPS_PER_BLK], sm_ms[WARPS_PER_BLK];
    __shared__ bool   s_is_last;
    if (lane == 0) { sm_ce[wid] = ce_sum; sm_ms[wid] = ms_sum; }
    __syncthreads();

    if (threadIdx.x == 0) {
        double bce = 0.0, bms = 0.0;
        #pragma unroll
        for (int j = 0; j < WARPS_PER_BLK; j++) { bce += sm_ce[j]; bms += sm_ms[j]; }
        g_pce[blockIdx.x] = bce;
        g_pms[blockIdx.x] = bms;
        __threadfence();
        unsigned prev = atomicAdd(&g_count, 1u);
        s_is_last = (prev == gridDim.x - 1);
    }
    __syncthreads();

    // ---- last-arriving block: reduce L2-hot partials, emit outputs ----
    if (s_is_last) {
        const int tid = threadIdx.x;
        const int nb  = gridDim.x;
        double ce = 0.0, ms = 0.0;
        for (int i = tid; i < nb; i += 128) { ce += g_pce[i]; ms += g_pms[i]; }

        __shared__ double red[256];
        red[tid] = ce; red[128 + tid] = ms;
        __syncthreads();
        #pragma unroll
        for (int off = 64; off > 0; off >>= 1) {
            if (tid < off) {
                red[tid]       += red[tid + off];
                red[128 + tid] += red[128 + tid + off];
            }
            __syncthreads();
        }

        if (tid == 0) {
            float ce_loss = (float)(red[0] / (double)B);
            if (!isfinite(ce_loss)) ce_loss = 0.0f;
            float proto_loss = (float)(red[128] / (double)B);
            float total = ce_loss + proto_loss;
            if (!isfinite(total)) total = ce_loss;
            out[0] = total;
            out[1] = ce_loss;
            out[2] = proto_loss;
            g_count = 0;          // reset for next graph replay
        }
    }
}

extern "C" void kernel_launch(void* const* d_in, const int* in_sizes, int n_in,
                              void* d_out, int out_size) {
    const float* logits   = (const float*)d_in[0];
    const int*   labels   = (const int*)d_in[1];
    const float* features = (const float*)d_in[2];
    const float* protos   = (const float*)d_in[3];
    float* out = (float*)d_out;

    const int B = in_sizes[1];                 // 16384
    const int C = in_sizes[0] / B;             // 1000
    const int D = in_sizes[2] / B;             // 512

    const int rows_per_block = WARPS_PER_BLK * ROWS_PER_WARP;   // 16
    const int blocks = (B + rows_per_block - 1) / rows_per_block;  // 1024
    row_kernel<<<blocks, 128>>>(logits, labels, features, protos, out, B, C, D);
}